// round 1
// baseline (speedup 1.0000x reference)
#include <cuda_runtime.h>
#include <cstdint>

// Problem constants (fixed by the reference)
#define NN 100000
#define EE 3200000
#define IN_DIM 256
#define HID 128
#define OUT_DIM 64

// Scratch (allocation-free rule: __device__ globals)
__device__ float g_h1[(size_t)NN * HID];   // fc1 output
__device__ float g_h2[(size_t)NN * HID];   // spmm accumulator

// ---------------------------------------------------------------------------
// Kernel 1: h1 = features @ W1 + b1   (M=100000, K=256, N=128)
// Tiling: BM=64, BN=128(=full HID), BK=16; 256 threads; 8x4 per-thread tile.
// ---------------------------------------------------------------------------
#define BM 64
#define BN 128
#define BK 16
#define TM 8
#define TN 4

__global__ __launch_bounds__(256) void gemm1_kernel(
    const float* __restrict__ A,    // [NN, IN_DIM]
    const float* __restrict__ W1,   // [IN_DIM, HID]
    const float* __restrict__ b1)   // [HID]
{
    __shared__ float As[BK][BM];
    __shared__ float Bs[BK][BN];

    const int block_m = blockIdx.x * BM;
    const int tid = threadIdx.x;
    const int tx = tid & 31;   // 0..31 : column group (TN=4 cols)
    const int ty = tid >> 5;   // 0..7  : row group   (TM=8 rows)

    float acc[TM][TN];
#pragma unroll
    for (int i = 0; i < TM; i++)
#pragma unroll
        for (int j = 0; j < TN; j++) acc[i][j] = 0.0f;

    // A-tile load mapping: 64 rows x 16 cols = 256 float4 (one per thread)
    const int arow  = tid >> 2;        // 0..63
    const int acol4 = (tid & 3) << 2;  // 0,4,8,12
    const int am = block_m + arow;
    const bool arow_ok = (am < NN);

    for (int k0 = 0; k0 < IN_DIM; k0 += BK) {
        // --- load A tile (transposed into k-major) ---
        float4 av = make_float4(0.f, 0.f, 0.f, 0.f);
        if (arow_ok)
            av = *(const float4*)(A + (size_t)am * IN_DIM + k0 + acol4);
        As[acol4 + 0][arow] = av.x;
        As[acol4 + 1][arow] = av.y;
        As[acol4 + 2][arow] = av.z;
        As[acol4 + 3][arow] = av.w;

        // --- load B tile: 16 x 128 floats = 512 float4, 2 per thread ---
#pragma unroll
        for (int r = 0; r < 2; r++) {
            int f4 = tid + 256 * r;        // 0..511
            int bk = f4 >> 5;              // row in tile (128/4 = 32 f4 per row)
            int bn = (f4 & 31) << 2;       // col
            *(float4*)&Bs[bk][bn] =
                *(const float4*)(W1 + (size_t)(k0 + bk) * HID + bn);
        }
        __syncthreads();

#pragma unroll
        for (int kk = 0; kk < BK; kk++) {
            float af[TM], bf[TN];
#pragma unroll
            for (int i = 0; i < TM; i++) af[i] = As[kk][ty * TM + i];
            // TN=4 contiguous -> single LDS.128
            float4 b4 = *(float4*)&Bs[kk][tx * TN];
            bf[0] = b4.x; bf[1] = b4.y; bf[2] = b4.z; bf[3] = b4.w;
#pragma unroll
            for (int i = 0; i < TM; i++)
#pragma unroll
                for (int j = 0; j < TN; j++)
                    acc[i][j] = fmaf(af[i], bf[j], acc[i][j]);
        }
        __syncthreads();
    }

    // epilogue: + bias, store float4
    const float4 bias = *(const float4*)(b1 + tx * TN);
#pragma unroll
    for (int i = 0; i < TM; i++) {
        int m = block_m + ty * TM + i;
        if (m < NN) {
            float4 v;
            v.x = acc[i][0] + bias.x;
            v.y = acc[i][1] + bias.y;
            v.z = acc[i][2] + bias.z;
            v.w = acc[i][3] + bias.w;
            *(float4*)(g_h1 + (size_t)m * HID + tx * TN) = v;
        }
    }
}

// ---------------------------------------------------------------------------
// Kernel 2: zero g_h2 (12.8M floats -> 3.2M float4)
// ---------------------------------------------------------------------------
__global__ __launch_bounds__(256) void zero_h2_kernel()
{
    size_t i = (size_t)blockIdx.x * blockDim.x + threadIdx.x;
    if (i < (size_t)NN * HID / 4)
        ((float4*)g_h2)[i] = make_float4(0.f, 0.f, 0.f, 0.f);
}

// ---------------------------------------------------------------------------
// Kernel 3: SpMM scatter-add. One warp per edge.
//   lane handles float4 slice of the 128-wide row; vector red.global.add.
// ---------------------------------------------------------------------------
__device__ __forceinline__ void red_add_v4(float* addr, float4 v)
{
    asm volatile("red.global.add.v4.f32 [%0], {%1, %2, %3, %4};"
                 :: "l"(addr), "f"(v.x), "f"(v.y), "f"(v.z), "f"(v.w)
                 : "memory");
}

__global__ __launch_bounds__(256) void spmm_kernel(
    const int* __restrict__ erow,
    const int* __restrict__ ecol,
    const float* __restrict__ eval)
{
    const int warp = (blockIdx.x * blockDim.x + threadIdx.x) >> 5;
    const int lane = threadIdx.x & 31;
    if (warp >= EE) return;

    const int   r = __ldg(erow + warp);   // uniform across warp -> 1 LDG, bcast
    const int   c = __ldg(ecol + warp);
    const float v = __ldg(eval + warp);

    float4 h = *(const float4*)(g_h1 + (size_t)c * HID + (lane << 2));
    h.x *= v; h.y *= v; h.z *= v; h.w *= v;
    red_add_v4(g_h2 + (size_t)r * HID + (lane << 2), h);
}

// ---------------------------------------------------------------------------
// Kernel 4: out = log_softmax( relu(h2) @ W2 + b2 )
// 256 threads/block = 8 warps = 8 nodes. W2 (32KB) staged in shared.
// Each lane computes 2 output columns (lane, lane+32); shuffle reductions.
// ---------------------------------------------------------------------------
__global__ __launch_bounds__(256) void mlp2_kernel(
    const float* __restrict__ W2,   // [HID, OUT_DIM]
    const float* __restrict__ b2,   // [OUT_DIM]
    float* __restrict__ out)        // [NN, OUT_DIM]
{
    __shared__ float sW2[HID * OUT_DIM];   // 32 KB
    __shared__ float sh[8][HID];           // 4 KB

    const int tid = threadIdx.x;
    for (int i = tid; i < HID * OUT_DIM; i += 256) sW2[i] = W2[i];
    __syncthreads();

    const int warp = tid >> 5;
    const int lane = tid & 31;
    const int node = blockIdx.x * 8 + warp;
    if (node >= NN) return;

    // load this node's h2 row with ReLU into per-warp shared slab
    float4 hv = *(const float4*)(g_h2 + (size_t)node * HID + (lane << 2));
    sh[warp][(lane << 2) + 0] = fmaxf(hv.x, 0.f);
    sh[warp][(lane << 2) + 1] = fmaxf(hv.y, 0.f);
    sh[warp][(lane << 2) + 2] = fmaxf(hv.z, 0.f);
    sh[warp][(lane << 2) + 3] = fmaxf(hv.w, 0.f);
    __syncwarp();

    float acc0 = __ldg(b2 + lane);
    float acc1 = __ldg(b2 + lane + 32);
#pragma unroll 8
    for (int k = 0; k < HID; k++) {
        float h = sh[warp][k];                     // broadcast
        acc0 = fmaf(h, sW2[k * OUT_DIM + lane],      acc0);
        acc1 = fmaf(h, sW2[k * OUT_DIM + lane + 32], acc1);
    }

    // log_softmax over the 64 logits held 2-per-lane
    float m = fmaxf(acc0, acc1);
#pragma unroll
    for (int o = 16; o > 0; o >>= 1)
        m = fmaxf(m, __shfl_xor_sync(0xffffffffu, m, o));
    float s = __expf(acc0 - m) + __expf(acc1 - m);
#pragma unroll
    for (int o = 16; o > 0; o >>= 1)
        s += __shfl_xor_sync(0xffffffffu, s, o);
    const float lse = m + __logf(s);

    out[(size_t)node * OUT_DIM + lane]      = acc0 - lse;
    out[(size_t)node * OUT_DIM + lane + 32] = acc1 - lse;
}

// ---------------------------------------------------------------------------
// Launch
// inputs: 0 features [NN*IN_DIM] f32, 1 edge_row [EE] i32, 2 edge_col [EE] i32,
//         3 edge_val [EE] f32, 4 W1 [IN_DIM*HID] f32, 5 b1 [HID] f32,
//         6 W2 [HID*OUT_DIM] f32, 7 b2 [OUT_DIM] f32
// ---------------------------------------------------------------------------
extern "C" void kernel_launch(void* const* d_in, const int* in_sizes, int n_in,
                              void* d_out, int out_size)
{
    const float* features = (const float*)d_in[0];
    const int*   erow     = (const int*)  d_in[1];
    const int*   ecol     = (const int*)  d_in[2];
    const float* eval     = (const float*)d_in[3];
    const float* W1       = (const float*)d_in[4];
    const float* b1       = (const float*)d_in[5];
    const float* W2       = (const float*)d_in[6];
    const float* b2       = (const float*)d_in[7];
    float* out = (float*)d_out;

    // 1) fc1
    gemm1_kernel<<<(NN + BM - 1) / BM, 256>>>(features, W1, b1);

    // 2) zero accumulator
    zero_h2_kernel<<<((NN * HID / 4) + 255) / 256, 256>>>();

    // 3) spmm scatter-add (warp per edge)
    {
        const long long total_threads = (long long)EE * 32;
        const int blocks = (int)((total_threads + 255) / 256);
        spmm_kernel<<<blocks, 256>>>(erow, ecol, eval);
    }

    // 4) fc2 + relu + log_softmax
    mlp2_kernel<<<(NN + 7) / 8, 256>>>(W2, b2, out);
}